// round 6
// baseline (speedup 1.0000x reference)
#include <cuda_runtime.h>
#include <math.h>

#define N_NODES 100000
#define E_EDGES 1600000
#define CAP 80                     // padded slots per dst (max degree ~45)

// ---------------- scratch (device globals; no allocation allowed) ----------
__device__ float g_z[N_NODES * 32];        // 12.8 MB (L2-resident)
__device__ float g_sl[N_NODES];
__device__ float g_sr[N_NODES];
__device__ int   g_cnt[N_NODES];           // scatter cursor == degree
__device__ uint2 g_pk[N_NODES * CAP];      // padded CSR payload: (src, w)

// ---------------------------------------------------------------------------
// GEMM: z = h @ fc_w^T (100000x128 @ 128x32) + s_l/s_r projections.
// 128 rows x 32 cols per block, 256 threads, 2 rows x 8 cols per thread.
// Double-buffered k-chunks (32 k each): prefetch chunk kc+1 into registers
// (4 back-to-back LDG.128/thread -> deep MLP, DRAM latency hidden) while
// computing chunk kc from smem. h smem uses XOR swizzle (no padding) so
// h(32KB,2buf) + w(16KB) = exactly 48KB static smem -> 4 blocks/SM.
// ---------------------------------------------------------------------------
__global__ __launch_bounds__(256, 4)
void gemm_kernel(const float* __restrict__ h,
                 const float* __restrict__ fc_w,
                 const float* __restrict__ attn_w) {
    __shared__ float h_s[2 * 128 * 32];  // [buf][row][k], k XOR-swizzled
    __shared__ float w_s[128 * 32];      // [k][col], unpadded

    int tid  = threadIdx.x;
    int colg = tid & 3;       // 4 col groups of 8 cols
    int rowg = tid >> 2;      // 0..63; rows rowg and rowg+64

    // zero scatter cursors (782*256 = 200192 >= N_NODES)
    int zid = blockIdx.x * 256 + tid;
    if (zid < N_NODES) g_cnt[zid] = 0;

    // stage w transposed: w_s[k*32+col] = fc_w[col*128+k]
    for (int i = tid; i < 4096; i += 256) {
        int col = i >> 7, k = i & 127;
        w_s[k * 32 + col] = fc_w[i];
    }

    int rowbase = blockIdx.x * 128;

    // prefetch registers: 4 float4 per thread per chunk
    float4 pf[4];
    int prow[4], pj4[4];
#pragma unroll
    for (int q = 0; q < 4; q++) {
        int idx = q * 256 + tid;        // 0..1023
        prow[q] = idx >> 3;             // 0..127
        pj4[q]  = idx & 7;              // float4 index within 32-k chunk
    }

    // load chunk 0
#pragma unroll
    for (int q = 0; q < 4; q++) {
        int grow = rowbase + prow[q];
        pf[q] = (grow < N_NODES)
              ? *(const float4*)&h[(size_t)grow * 128 + pj4[q] * 4]
              : make_float4(0.f, 0.f, 0.f, 0.f);
    }
    // store chunk 0 to buf 0 (XOR swizzle: float4 slot j4 -> j4 ^ (row&7))
#pragma unroll
    for (int q = 0; q < 4; q++)
        *(float4*)&h_s[prow[q] * 32 + 4 * (pj4[q] ^ (prow[q] & 7))] = pf[q];
    __syncthreads();

    unsigned long long acc[2][4];   // [row][col pair]
#pragma unroll
    for (int i = 0; i < 2; i++)
#pragma unroll
        for (int c = 0; c < 4; c++) acc[i][c] = 0ull;

    int sw = 4 * ((rowg & 7));      // XOR swizzle offset for this thread's rows

    for (int kc = 0; kc < 4; kc++) {
        // issue next chunk's loads early (latency overlapped with compute)
        if (kc < 3) {
#pragma unroll
            for (int q = 0; q < 4; q++) {
                int grow = rowbase + prow[q];
                pf[q] = (grow < N_NODES)
                      ? *(const float4*)&h[(size_t)grow * 128 + (kc + 1) * 32 + pj4[q] * 4]
                      : make_float4(0.f, 0.f, 0.f, 0.f);
            }
        }

        const float* hb = &h_s[(kc & 1) * 4096];
#pragma unroll
        for (int k4 = 0; k4 < 8; k4++) {
            int koff = 4 * k4 ^ sw;
            float4 h0 = *(const float4*)&hb[rowg * 32 + koff];
            float4 h1 = *(const float4*)&hb[(rowg + 64) * 32 + koff];
#pragma unroll
            for (int j = 0; j < 4; j++) {
                int k = kc * 32 + k4 * 4 + j;
                ulonglong2 wv0 = *(const ulonglong2*)&w_s[k * 32 + colg * 8];
                ulonglong2 wv1 = *(const ulonglong2*)&w_s[k * 32 + colg * 8 + 4];
                float f0 = (j == 0) ? h0.x : (j == 1) ? h0.y : (j == 2) ? h0.z : h0.w;
                float f1 = (j == 0) ? h1.x : (j == 1) ? h1.y : (j == 2) ? h1.z : h1.w;
                unsigned long long hh0, hh1;
                asm("mov.b64 %0, {%1, %1};" : "=l"(hh0) : "r"(__float_as_uint(f0)));
                asm("mov.b64 %0, {%1, %1};" : "=l"(hh1) : "r"(__float_as_uint(f1)));
                asm("fma.rn.f32x2 %0, %1, %2, %0;" : "+l"(acc[0][0]) : "l"(hh0), "l"(wv0.x));
                asm("fma.rn.f32x2 %0, %1, %2, %0;" : "+l"(acc[0][1]) : "l"(hh0), "l"(wv0.y));
                asm("fma.rn.f32x2 %0, %1, %2, %0;" : "+l"(acc[0][2]) : "l"(hh0), "l"(wv1.x));
                asm("fma.rn.f32x2 %0, %1, %2, %0;" : "+l"(acc[0][3]) : "l"(hh0), "l"(wv1.y));
                asm("fma.rn.f32x2 %0, %1, %2, %0;" : "+l"(acc[1][0]) : "l"(hh1), "l"(wv0.x));
                asm("fma.rn.f32x2 %0, %1, %2, %0;" : "+l"(acc[1][1]) : "l"(hh1), "l"(wv0.y));
                asm("fma.rn.f32x2 %0, %1, %2, %0;" : "+l"(acc[1][2]) : "l"(hh1), "l"(wv1.x));
                asm("fma.rn.f32x2 %0, %1, %2, %0;" : "+l"(acc[1][3]) : "l"(hh1), "l"(wv1.y));
            }
        }

        if (kc < 3) {
            __syncthreads();   // all warps done reading buf (kc+1)&1
#pragma unroll
            for (int q = 0; q < 4; q++)
                *(float4*)&h_s[((kc + 1) & 1) * 4096 + prow[q] * 32
                               + 4 * (pj4[q] ^ (prow[q] & 7))] = pf[q];
            __syncthreads();
        }
    }

    // epilogue: 2 rows x 8 cols per thread; s_l/s_r reduced over 4 colg lanes
    int colbase = colg * 8;
#pragma unroll
    for (int i = 0; i < 2; i++) {
        int grow = rowbase + rowg + 64 * i;
        float v[8];
#pragma unroll
        for (int c = 0; c < 4; c++) {
            unsigned int lo, hi;
            asm("mov.b64 {%0, %1}, %2;" : "=r"(lo), "=r"(hi) : "l"(acc[i][c]));
            v[c * 2]     = __uint_as_float(lo);
            v[c * 2 + 1] = __uint_as_float(hi);
        }
        if (grow < N_NODES) {
            *(float4*)&g_z[grow * 32 + colbase]     = make_float4(v[0], v[1], v[2], v[3]);
            *(float4*)&g_z[grow * 32 + colbase + 4] = make_float4(v[4], v[5], v[6], v[7]);
        }
        float pl = 0.f, pr = 0.f;
#pragma unroll
        for (int c = 0; c < 8; c++) {
            pl += v[c] * __ldg(&attn_w[colbase + c]);
            pr += v[c] * __ldg(&attn_w[32 + colbase + c]);
        }
        pl += __shfl_down_sync(0xffffffffu, pl, 2, 4);
        pr += __shfl_down_sync(0xffffffffu, pr, 2, 4);
        pl += __shfl_down_sync(0xffffffffu, pl, 1, 4);
        pr += __shfl_down_sync(0xffffffffu, pr, 1, 4);
        if (colg == 0 && grow < N_NODES) {
            g_sl[grow] = pl;
            g_sr[grow] = pr;
        }
    }
}

// ---------------------------------------------------------------------------
// scatter: w = exp(leaky_relu(s_l[src]+s_r[dst])) (no max subtraction —
// mathematically identical softmax; |e| bounded ~20 so exp is safe in fp32).
// ---------------------------------------------------------------------------
__device__ __forceinline__ void scatter_one(int s, int d) {
    float e = g_sl[s] + g_sr[d];
    e = (e > 0.0f) ? e : 0.01f * e;
    float w = __expf(e);
    int local = atomicAdd(&g_cnt[d], 1);
    if (local < CAP)
        g_pk[d * CAP + local] = make_uint2((unsigned)s, __float_as_uint(w));
}

__global__ void scatter_kernel(const int* __restrict__ src,
                               const int* __restrict__ dst) {
    int i = blockIdx.x * blockDim.x + threadIdx.x;
    if (i >= E_EDGES / 4) return;
    int4 s4 = ((const int4*)src)[i];
    int4 d4 = ((const int4*)dst)[i];
    scatter_one(s4.x, d4.x);
    scatter_one(s4.y, d4.y);
    scatter_one(s4.z, d4.z);
    scatter_one(s4.w, d4.w);
}

// ---------------------------------------------------------------------------
// aggregate: one warp per dst node; lane = output column. 8-slot unroll with
// hoisted loads for deep MLP on the L2-resident z gathers.
// ---------------------------------------------------------------------------
__global__ void agg_kernel(float* __restrict__ out) {
    int node = blockIdx.x * 8 + (threadIdx.x >> 5);   // 12500*8 = 100000 exact
    int lane = threadIdx.x & 31;
    int cnt = g_cnt[node];
    if (cnt > CAP) cnt = CAP;
    const uint2* row = &g_pk[node * CAP];

    float acc = 0.f, den = 0.f;
    int j = 0;
    for (; j + 8 <= cnt; j += 8) {
        uint4 q0 = __ldg((const uint4*)&row[j]);
        uint4 q1 = __ldg((const uint4*)&row[j + 2]);
        uint4 q2 = __ldg((const uint4*)&row[j + 4]);
        uint4 q3 = __ldg((const uint4*)&row[j + 6]);
        float z0 = g_z[q0.x * 32 + lane];
        float z1 = g_z[q0.z * 32 + lane];
        float z2 = g_z[q1.x * 32 + lane];
        float z3 = g_z[q1.z * 32 + lane];
        float z4 = g_z[q2.x * 32 + lane];
        float z5 = g_z[q2.z * 32 + lane];
        float z6 = g_z[q3.x * 32 + lane];
        float z7 = g_z[q3.z * 32 + lane];
        float w0 = __uint_as_float(q0.y), w1 = __uint_as_float(q0.w);
        float w2 = __uint_as_float(q1.y), w3 = __uint_as_float(q1.w);
        float w4 = __uint_as_float(q2.y), w5 = __uint_as_float(q2.w);
        float w6 = __uint_as_float(q3.y), w7 = __uint_as_float(q3.w);
        den += ((w0 + w1) + (w2 + w3)) + ((w4 + w5) + (w6 + w7));
        acc += w0 * z0; acc += w1 * z1; acc += w2 * z2; acc += w3 * z3;
        acc += w4 * z4; acc += w5 * z5; acc += w6 * z6; acc += w7 * z7;
    }
    for (; j + 2 <= cnt; j += 2) {
        uint4 q = __ldg((const uint4*)&row[j]);
        float w0 = __uint_as_float(q.y), w1 = __uint_as_float(q.w);
        den += w0 + w1;
        acc += w0 * g_z[q.x * 32 + lane];
        acc += w1 * g_z[q.z * 32 + lane];
    }
    for (; j < cnt; j++) {
        uint2 p = __ldg(&row[j]);
        float w = __uint_as_float(p.y);
        den += w;
        acc += w * g_z[p.x * 32 + lane];
    }
    out[node * 32 + lane] = (cnt > 0) ? acc / den : 0.f;
}

// ---------------------------------------------------------------------------
extern "C" void kernel_launch(void* const* d_in, const int* in_sizes, int n_in,
                              void* d_out, int out_size) {
    const float* h      = (const float*)d_in[0];
    const int*   src    = (const int*)d_in[1];
    const int*   dst    = (const int*)d_in[2];
    const float* fc_w   = (const float*)d_in[3];
    const float* attn_w = (const float*)d_in[4];
    float* out = (float*)d_out;

    gemm_kernel   <<<782, 256>>>(h, fc_w, attn_w);
    scatter_kernel<<<1563, 256>>>(src, dst);
    agg_kernel    <<<12500, 256>>>(out);
}

// round 7
// speedup vs baseline: 1.4675x; 1.4675x over previous
#include <cuda_runtime.h>
#include <cuda_fp16.h>
#include <math.h>

#define N_NODES 100000
#define E_EDGES 1600000
#define CAP 80                     // padded slots per dst (max degree ~45)

// ---------------- scratch (device globals; no allocation allowed) ----------
__device__ __half g_zh[N_NODES * 32];      // z in fp16 (6.4 MB, L2-resident)
__device__ float  g_sl[N_NODES];
__device__ float  g_sr[N_NODES];
__device__ int    g_cnt[N_NODES];          // scatter cursor == degree
__device__ uint2  g_pk[N_NODES * CAP];     // padded CSR payload: (src, w)

// ---------------------------------------------------------------------------
// GEMM (proven R5 structure): z = h @ fc_w^T + s_l/s_r projections.
// 128 rows x 32 cols per block, 128 threads, 4 rows x 8 cols per thread.
// Broadcast-aware mapping (colg = tid&3, rowg = tid>>2), f32x2 FMAs.
// Only change vs R5: z stored as half2 (one uint4 per row-slice).
// ---------------------------------------------------------------------------
#define SW 36
#define SH 36

__global__ __launch_bounds__(128, 6)
void gemm_kernel(const float* __restrict__ h,
                 const float* __restrict__ fc_w,
                 const float* __restrict__ attn_w) {
    __shared__ float w_s[128 * SW];   // [k][col], pad 36
    __shared__ float h_s[128 * SH];   // [row][k-in-chunk], pad 36 (32 used)
    __shared__ float a_s[64];

    int tid  = threadIdx.x;
    int colg = tid & 3;       // 4 col groups of 8
    int rowg = tid >> 2;      // 32 row groups; rows = rowg + 32*i

    // zero scatter cursors (782*128 = 100096 >= N_NODES)
    int zid = blockIdx.x * 128 + tid;
    if (zid < N_NODES) g_cnt[zid] = 0;

    // stage w transposed: w_s[k][col] = fc_w[col*128 + k]
    for (int i = tid; i < 4096; i += 128) {
        int col = i >> 7, k = i & 127;
        w_s[k * SW + col] = fc_w[i];
    }
    if (tid < 64) a_s[tid] = attn_w[tid];

    int rowbase = blockIdx.x * 128;

    unsigned long long acc[4][4];    // [row i][col pair] = 4 rows x 8 cols
#pragma unroll
    for (int i = 0; i < 4; i++)
#pragma unroll
        for (int c = 0; c < 4; c++) acc[i][c] = 0ull;

    for (int kc = 0; kc < 4; kc++) {
        __syncthreads();
        // stage h chunk: 128 rows x 32 k
#pragma unroll
        for (int q = 0; q < 8; q++) {
            int idx = tid + 128 * q;         // 0..1023
            int row = idx >> 3, c4 = idx & 7;
            int grow = rowbase + row;
            float4 hv = make_float4(0.f, 0.f, 0.f, 0.f);
            if (grow < N_NODES)
                hv = *(const float4*)&h[(size_t)grow * 128 + kc * 32 + c4 * 4];
            *(float4*)&h_s[row * SH + c4 * 4] = hv;
        }
        __syncthreads();

#pragma unroll
        for (int kk4 = 0; kk4 < 8; kk4++) {
            float4 hv[4];
#pragma unroll
            for (int i = 0; i < 4; i++)
                hv[i] = *(const float4*)&h_s[(rowg + 32 * i) * SH + kk4 * 4];
#pragma unroll
            for (int j = 0; j < 4; j++) {
                int k = kc * 32 + kk4 * 4 + j;
                ulonglong2 wv0 = *(const ulonglong2*)&w_s[k * SW + colg * 8];
                ulonglong2 wv1 = *(const ulonglong2*)&w_s[k * SW + colg * 8 + 4];
#pragma unroll
                for (int i = 0; i < 4; i++) {
                    float hf = (j == 0) ? hv[i].x : (j == 1) ? hv[i].y
                             : (j == 2) ? hv[i].z : hv[i].w;
                    unsigned long long hh;
                    asm("mov.b64 %0, {%1, %1};" : "=l"(hh) : "r"(__float_as_uint(hf)));
                    asm("fma.rn.f32x2 %0, %1, %2, %0;"
                        : "+l"(acc[i][0]) : "l"(hh), "l"(wv0.x));
                    asm("fma.rn.f32x2 %0, %1, %2, %0;"
                        : "+l"(acc[i][1]) : "l"(hh), "l"(wv0.y));
                    asm("fma.rn.f32x2 %0, %1, %2, %0;"
                        : "+l"(acc[i][2]) : "l"(hh), "l"(wv1.x));
                    asm("fma.rn.f32x2 %0, %1, %2, %0;"
                        : "+l"(acc[i][3]) : "l"(hh), "l"(wv1.y));
                }
            }
        }
    }

    // epilogue: unpack 8 cols per row, store z as half2x4, reduce s_l/s_r
    int colbase = colg * 8;
#pragma unroll
    for (int i = 0; i < 4; i++) {
        int grow = rowbase + rowg + 32 * i;
        float v[8];
#pragma unroll
        for (int c = 0; c < 4; c++) {
            unsigned int lo, hi;
            asm("mov.b64 {%0, %1}, %2;" : "=r"(lo), "=r"(hi) : "l"(acc[i][c]));
            v[c * 2]     = __uint_as_float(lo);
            v[c * 2 + 1] = __uint_as_float(hi);
        }
        if (grow < N_NODES) {
            __half2 p0 = __floats2half2_rn(v[0], v[1]);
            __half2 p1 = __floats2half2_rn(v[2], v[3]);
            __half2 p2 = __floats2half2_rn(v[4], v[5]);
            __half2 p3 = __floats2half2_rn(v[6], v[7]);
            uint4 pk;
            pk.x = *(unsigned int*)&p0;
            pk.y = *(unsigned int*)&p1;
            pk.z = *(unsigned int*)&p2;
            pk.w = *(unsigned int*)&p3;
            *(uint4*)&g_zh[grow * 32 + colbase] = pk;   // 16B aligned
        }
        float pl = 0.f, pr = 0.f;
#pragma unroll
        for (int c = 0; c < 8; c++) {
            pl += v[c] * a_s[colbase + c];
            pr += v[c] * a_s[32 + colbase + c];
        }
        pl += __shfl_down_sync(0xffffffffu, pl, 2, 4);
        pr += __shfl_down_sync(0xffffffffu, pr, 2, 4);
        pl += __shfl_down_sync(0xffffffffu, pl, 1, 4);
        pr += __shfl_down_sync(0xffffffffu, pr, 1, 4);
        if (colg == 0 && grow < N_NODES) {
            g_sl[grow] = pl;
            g_sr[grow] = pr;
        }
    }
}

// ---------------------------------------------------------------------------
// scatter: w = exp(leaky_relu(s_l[src]+s_r[dst])) (no max subtraction —
// mathematically identical softmax; |e| bounded ~20 so exp is safe in fp32).
// ---------------------------------------------------------------------------
__device__ __forceinline__ void scatter_one(int s, int d) {
    float e = g_sl[s] + g_sr[d];
    e = (e > 0.0f) ? e : 0.01f * e;
    float w = __expf(e);
    int local = atomicAdd(&g_cnt[d], 1);
    if (local < CAP)
        g_pk[d * CAP + local] = make_uint2((unsigned)s, __float_as_uint(w));
}

__global__ void scatter_kernel(const int* __restrict__ src,
                               const int* __restrict__ dst) {
    int i = blockIdx.x * blockDim.x + threadIdx.x;
    if (i >= E_EDGES / 4) return;
    int4 s4 = ((const int4*)src)[i];
    int4 d4 = ((const int4*)dst)[i];
    scatter_one(s4.x, d4.x);
    scatter_one(s4.y, d4.y);
    scatter_one(s4.z, d4.z);
    scatter_one(s4.w, d4.w);
}

// ---------------------------------------------------------------------------
// aggregate: 2 nodes per warp; half-warp per node, each lane owns 2 cols
// via half2. z rows are 64B (fp16) -> fully coalesced per half-warp.
// ---------------------------------------------------------------------------
__global__ void agg_kernel(float* __restrict__ out) {
    int warp  = blockIdx.x * 8 + (threadIdx.x >> 5);  // 6250*8 = 50000 warps
    int lane  = threadIdx.x & 31;
    int node  = warp * 2 + (lane >> 4);               // 2 nodes per warp
    int lanec = lane & 15;                            // half2 column index

    int cnt = g_cnt[node];
    if (cnt > CAP) cnt = CAP;
    const uint2* row = &g_pk[node * CAP];
    const __half2* zb = (const __half2*)g_zh;

    float ax = 0.f, ay = 0.f, den = 0.f;
    int j = 0;
    for (; j + 4 <= cnt; j += 4) {
        uint4 q0 = __ldg((const uint4*)&row[j]);       // slots j, j+1
        uint4 q1 = __ldg((const uint4*)&row[j + 2]);   // slots j+2, j+3
        float2 z0 = __half22float2(zb[q0.x * 16 + lanec]);
        float2 z1 = __half22float2(zb[q0.z * 16 + lanec]);
        float2 z2 = __half22float2(zb[q1.x * 16 + lanec]);
        float2 z3 = __half22float2(zb[q1.z * 16 + lanec]);
        float w0 = __uint_as_float(q0.y), w1 = __uint_as_float(q0.w);
        float w2 = __uint_as_float(q1.y), w3 = __uint_as_float(q1.w);
        den += (w0 + w1) + (w2 + w3);
        ax += w0 * z0.x; ay += w0 * z0.y;
        ax += w1 * z1.x; ay += w1 * z1.y;
        ax += w2 * z2.x; ay += w2 * z2.y;
        ax += w3 * z3.x; ay += w3 * z3.y;
    }
    for (; j < cnt; j++) {
        uint2 p = __ldg(&row[j]);
        float w = __uint_as_float(p.y);
        float2 z = __half22float2(zb[p.x * 16 + lanec]);
        den += w;
        ax += w * z.x;
        ay += w * z.y;
    }
    float inv = (cnt > 0) ? 1.0f / den : 0.0f;
    *(float2*)&out[node * 32 + lanec * 2] = make_float2(ax * inv, ay * inv);
}

// ---------------------------------------------------------------------------
extern "C" void kernel_launch(void* const* d_in, const int* in_sizes, int n_in,
                              void* d_out, int out_size) {
    const float* h      = (const float*)d_in[0];
    const int*   src    = (const int*)d_in[1];
    const int*   dst    = (const int*)d_in[2];
    const float* fc_w   = (const float*)d_in[3];
    const float* attn_w = (const float*)d_in[4];
    float* out = (float*)d_out;

    gemm_kernel   <<<782, 128>>>(h, fc_w, attn_w);
    scatter_kernel<<<1563, 256>>>(src, dst);
    agg_kernel    <<<6250, 256>>>(out);
}